// round 13
// baseline (speedup 1.0000x reference)
#include <cuda_runtime.h>

// GeneralMechanismODE — single-touch stream (96 B in, 32 B out per row).
// R13: the proven-best R7 configuration (3 samples: 28.7/29.4/29.15 — the
// ONLY config family under 31.2):
//   block 128 (churn optimum: 256 and 64 both regress),
//   1 row/thread, no loop-carried hazards (persistent/multi-row regress),
//   4 front-batched LDG.128 .cs (evict-first; default policy regresses),
//   2 STG.128 .wt (no L2 dirty allocation between graph replays),
//   v8 256-bit accesses rejected (deterministically worse wall),
//   L2 prefetch hints rejected (neutral).
// Micro-trim: guard-free variant dispatched when B % blockDim == 0
// (true here: 2,000,000 % 128 == 0) — drops the ISETP/BRA prologue.
// Analysis says we are at the roofline: 192 MB compulsory traffic at
// ~6.7 TB/s effective, mixed-stream DRAM plateau, compute pipes idle.

__device__ __forceinline__ void ode_row(const float4 ylo, const float4 yhi,
                                        const float4 f, const float4 r,
                                        float4& olo, float4& ohi)
{
    float v0 = f.x * ylo.x * yhi.x - r.x * ylo.y;          // kf0*E*A  - kr0*EA
    float v1 = f.y * ylo.y * yhi.y - r.y * ylo.w;          // kf1*EA*B - kr1*EAB
    float v2 = f.z * ylo.w         - r.z * ylo.z * yhi.z;  // kf2*EAB  - kr2*EQ*P
    float v3 = f.w * ylo.z         - r.w * ylo.x * yhi.w;  // kf3*EQ   - kr3*E*Q

    olo.x = v3 - v0;   // dE
    olo.y = v0 - v1;   // dEA
    olo.z = v2 - v3;   // dEQ
    olo.w = v1 - v2;   // dEAB
    ohi.x = -v0;       // dA
    ohi.y = -v1;       // dB
    ohi.z = v2;        // dP
    ohi.w = v3;        // dQ
}

// Exact-grid variant: every thread maps to a valid row, no bounds check.
__global__ __launch_bounds__(128) void ode_kernel13_exact(
    const float4* __restrict__ y,
    const float4* __restrict__ kf,
    const float4* __restrict__ kr,
    float4* __restrict__ out)
{
    int b = blockIdx.x * blockDim.x + threadIdx.x;

    float4 ylo = __ldcs(&y[2 * b + 0]);
    float4 yhi = __ldcs(&y[2 * b + 1]);
    float4 f   = __ldcs(&kf[b]);
    float4 r   = __ldcs(&kr[b]);

    float4 olo, ohi;
    ode_row(ylo, yhi, f, r, olo, ohi);

    __stwt(&out[2 * b + 0], olo);
    __stwt(&out[2 * b + 1], ohi);
}

// Guarded fallback for non-multiple B.
__global__ __launch_bounds__(128) void ode_kernel13_guard(
    const float4* __restrict__ y,
    const float4* __restrict__ kf,
    const float4* __restrict__ kr,
    float4* __restrict__ out,
    int B)
{
    int b = blockIdx.x * blockDim.x + threadIdx.x;
    if (b >= B) return;

    float4 ylo = __ldcs(&y[2 * b + 0]);
    float4 yhi = __ldcs(&y[2 * b + 1]);
    float4 f   = __ldcs(&kf[b]);
    float4 r   = __ldcs(&kr[b]);

    float4 olo, ohi;
    ode_row(ylo, yhi, f, r, olo, ohi);

    __stwt(&out[2 * b + 0], olo);
    __stwt(&out[2 * b + 1], ohi);
}

extern "C" void kernel_launch(void* const* d_in, const int* in_sizes, int n_in,
                              void* d_out, int out_size)
{
    // metadata order: t (1), y (B*8), forward_rates (B*4), reverse_rates (B*4)
    const float4* y  = (const float4*)d_in[1];
    const float4* kf = (const float4*)d_in[2];
    const float4* kr = (const float4*)d_in[3];
    float4* out = (float4*)d_out;

    int B = in_sizes[1] / 8;
    const int threads = 128;

    if (B % threads == 0) {
        ode_kernel13_exact<<<B / threads, threads>>>(y, kf, kr, out);
    } else {
        ode_kernel13_guard<<<(B + threads - 1) / threads, threads>>>(y, kf, kr, out, B);
    }
}

// round 14
// speedup vs baseline: 1.0088x; 1.0088x over previous
#include <cuda_runtime.h>

// GeneralMechanismODE — single-touch stream (96 B in, 32 B out per row).
// R14: full-density memory accesses via warp shuffle exchange.
// Problem identified: row-major float4 access puts lanes at 32 B stride, so
// each y-load / out-store wavefront touches 32 sectors at 16 B useful each —
// doubling LTS sector requests for 160 of the 192 MB (likely the true
// saturated resource behind the ~70% DRAM plateau).
// Fix: warp handles 32 rows = 64 contiguous float4. Two LANE-MAJOR dense
// LDG.128.cs (each 512 B fully dense), then 4x SHFL.XOR(1) re-pairs each
// lane with its row's (ylo, yhi). Reverse exchange before two dense
// STG.128.wt. Keeps the proven R7 instruction set (128-bit, .cs/.wt,
// block 128) — v8 rejected for deterministic wall regression.
//
// Mapping (warp w, lane l, k = l>>1):
//   load A = y4[64w + l], load B = y4[64w + 32 + l]
//   even lane 2k:  A = ylo(32w+k),    B = ylo(32w+16+k)
//   odd  lane 2k+1:A = yhi(32w+k),    B = yhi(32w+16+k)
//   lane 2k processes row 32w+k; lane 2k+1 processes row 32w+16+k
//   exchange: even sends B, odd sends A -> even recv yhi(own), odd recv ylo(own)
//   stores: reverse exchange (even sends ohi, odd sends olo).

__device__ __forceinline__ float4 shfl_xor1_f4(float4 v) {
    float4 o;
    o.x = __shfl_xor_sync(0xffffffffu, v.x, 1);
    o.y = __shfl_xor_sync(0xffffffffu, v.y, 1);
    o.z = __shfl_xor_sync(0xffffffffu, v.z, 1);
    o.w = __shfl_xor_sync(0xffffffffu, v.w, 1);
    return o;
}

__global__ __launch_bounds__(128) void ode_kernel14(
    const float4* __restrict__ y4,   // 2*B float4
    const float4* __restrict__ kf,   // B float4
    const float4* __restrict__ kr,   // B float4
    float4* __restrict__ out,        // 2*B float4
    int B)
{
    int tid  = blockIdx.x * blockDim.x + threadIdx.x;
    int w    = tid >> 5;          // global warp id: rows 32w .. 32w+31
    int lane = tid & 31;
    bool even = (lane & 1) == 0;

    // This thread's row (after exchange): even lane 2k -> 32w+k, odd -> 32w+16+k
    int row = 32 * w + ((lane & 1) ? 16 : 0) + (lane >> 1);
    if (row >= B) return;  // B % 128 == 0 here, so never taken; kept for safety

    // Dense lane-major loads: each LDG.128 covers 512 contiguous bytes.
    float4 A = __ldcs(&y4[64 * w + lane]);
    float4 Bv = __ldcs(&y4[64 * w + 32 + lane]);
    float4 f = __ldcs(&kf[row]);   // permuted lanes, same 512 B region: dense
    float4 r = __ldcs(&kr[row]);

    // Exchange: even lane sends B (ylo of partner's row), odd sends A (yhi of
    // partner's row); each receives the missing half of its own row.
    float4 recv = shfl_xor1_f4(even ? Bv : A);
    float4 ylo = even ? A    : recv;
    float4 yhi = even ? recv : Bv;

    float v0 = f.x * ylo.x * yhi.x - r.x * ylo.y;          // kf0*E*A  - kr0*EA
    float v1 = f.y * ylo.y * yhi.y - r.y * ylo.w;          // kf1*EA*B - kr1*EAB
    float v2 = f.z * ylo.w         - r.z * ylo.z * yhi.z;  // kf2*EAB  - kr2*EQ*P
    float v3 = f.w * ylo.z         - r.w * ylo.x * yhi.w;  // kf3*EQ   - kr3*E*Q

    float4 olo, ohi;
    olo.x = v3 - v0;   // dE
    olo.y = v0 - v1;   // dEA
    olo.z = v2 - v3;   // dEQ
    olo.w = v1 - v2;   // dEAB
    ohi.x = -v0;       // dA
    ohi.y = -v1;       // dB
    ohi.z = v2;        // dP
    ohi.w = v3;        // dQ

    // Reverse exchange for dense stores:
    // store A slot (fidx 64w+l):    even -> own olo, odd -> partner's ohi
    // store B slot (fidx 64w+32+l): even -> partner's olo, odd -> own ohi
    float4 recv2 = shfl_xor1_f4(even ? ohi : olo);
    float4 stA = even ? olo   : recv2;
    float4 stB = even ? recv2 : ohi;

    __stwt(&out[64 * w + lane], stA);
    __stwt(&out[64 * w + 32 + lane], stB);
}

extern "C" void kernel_launch(void* const* d_in, const int* in_sizes, int n_in,
                              void* d_out, int out_size)
{
    // metadata order: t (1), y (B*8), forward_rates (B*4), reverse_rates (B*4)
    const float4* y  = (const float4*)d_in[1];
    const float4* kf = (const float4*)d_in[2];
    const float4* kr = (const float4*)d_in[3];
    float4* out = (float4*)d_out;

    int B = in_sizes[1] / 8;
    const int threads = 128;
    int blocks = (B + threads - 1) / threads;
    ode_kernel14<<<blocks, threads>>>(y, kf, kr, out, B);
}